// round 4
// baseline (speedup 1.0000x reference)
#include <cuda_runtime.h>
#include <math.h>

// DCN collapsed-affine, round 4: fused chain kernel (internal barriers) +
// LDS-optimized main gather kernel (2 rows per warp).

#define EPSF 1e-5f

constexpr int Bn   = 4096;
constexpr int Fn   = 26;
constexpr int Vn   = 10000;
constexpr int Dn   = 64;
constexpr int D0   = 1664;   // Fn*Dn
constexpr int NUMB = 13;
constexpr int INW  = 1677;   // D0 + NUMB
constexpr int H1   = 1024;
constexpr int H2   = 512;
constexpr int H3   = 256;

constexpr int CG = 64;       // chain grid

// Scratch (device globals)
__device__ float g_v3p[CG][H2];
__device__ float g_v2p[CG][H1];
__device__ float g_up[CG][1792];
__device__ float g_q[1792];
__device__ float g_rp[7];
__device__ unsigned long long g_bar_chain;   // monotonic, multiple of CG across uses

__device__ __forceinline__ float warp_sum(float v) {
    #pragma unroll
    for (int o = 16; o; o >>= 1) v += __shfl_xor_sync(0xffffffffu, v, o);
    return v;
}

__device__ __forceinline__ void barrier_sync(unsigned long long* ctr, unsigned n) {
    __threadfence();
    __syncthreads();
    if (threadIdx.x == 0) {
        unsigned long long t = atomicAdd(ctr, 1ULL);
        unsigned long long target = (t / n + 1ULL) * (unsigned long long)n;
        while (*((volatile unsigned long long*)ctr) < target) __nanosleep(32);
    }
    __syncthreads();
    __threadfence();
}

// ---------------------------------------------------------------------------
// Fused chain: v3 -> v2 -> u -> (q, r).  grid=64, block=256.
__global__ __launch_bounds__(256) void k_chain(
    const float* __restrict__ bn0,
    const float* __restrict__ w1, const float* __restrict__ b1, const float* __restrict__ bn1,
    const float* __restrict__ w2, const float* __restrict__ b2, const float* __restrict__ bn2,
    const float* __restrict__ w3, const float* __restrict__ b3, const float* __restrict__ bn3,
    const float* __restrict__ pred_w, const float* __restrict__ pred_b) {

    __shared__ float ts[16];
    __shared__ float red[8];
    const int tid = threadIdx.x;
    const int bid = blockIdx.x;

    // ---- stage A: v3 partials.  i-chunk of 4 rows per block. ----
    {
        int i0 = bid * 4;
        if (tid < 4) {
            int i = i0 + tid;
            float a3 = bn3[i] * rsqrtf(bn3[3 * H3 + i] + EPSF);
            ts[tid] = a3 * pred_w[D0 + i];
        }
        __syncthreads();
        #pragma unroll
        for (int j = tid; j < H2; j += 256) {
            float acc = 0.f;
            #pragma unroll
            for (int i = 0; i < 4; i++) acc += w3[(i0 + i) * H2 + j] * ts[i];
            g_v3p[bid][j] = acc;
        }
    }
    barrier_sync(&g_bar_chain, CG);

    // ---- stage B: v2 partials.  i-chunk of 8. ----
    {
        int i0 = bid * 8;
        if (tid < 8) {
            int i = i0 + tid;
            float v3 = 0.f;
            #pragma unroll
            for (int p = 0; p < CG; p++) v3 += g_v3p[p][i];
            float a2 = bn2[i] * rsqrtf(bn2[3 * H2 + i] + EPSF);
            ts[tid] = a2 * v3;
        }
        __syncthreads();
        #pragma unroll
        for (int j = tid; j < H1; j += 256) {
            float acc = 0.f;
            #pragma unroll
            for (int i = 0; i < 8; i++) acc += w2[(i0 + i) * H1 + j] * ts[i];
            g_v2p[bid][j] = acc;
        }
    }
    barrier_sync(&g_bar_chain, CG);

    // ---- stage C: u partials.  i-chunk of 16. ----
    {
        int i0 = bid * 16;
        if (tid < 16) {
            int i = i0 + tid;
            float v2 = 0.f;
            #pragma unroll
            for (int p = 0; p < CG; p++) v2 += g_v2p[p][i];
            float a1 = bn1[i] * rsqrtf(bn1[3 * H1 + i] + EPSF);
            ts[tid] = a1 * v2;
        }
        __syncthreads();
        for (int j = tid; j < INW; j += 256) {
            float acc = 0.f;
            #pragma unroll
            for (int i = 0; i < 16; i++)
                acc += w1[(size_t)(i0 + i) * INW + j] * ts[i];
            g_up[bid][j] = acc;
        }
    }
    barrier_sync(&g_bar_chain, CG);

    // ---- stage D: q and r.  blocks 0..6 cover j in [0,1792). ----
    if (bid < 7) {
        int j = bid * 256 + tid;
        float r = 0.f;
        if (j < INW) {
            float u = 0.f;
            #pragma unroll
            for (int p = 0; p < CG; p++) u += g_up[p][j];
            float a0 = bn0[j] * rsqrtf(bn0[3 * INW + j] + EPSF);
            float c0 = bn0[INW + j] - bn0[2 * INW + j] * a0;
            g_q[j] = a0 * u;
            r = c0 * u;
        }
        if (j < H1) {
            float v2 = 0.f;
            #pragma unroll
            for (int p = 0; p < CG; p++) v2 += g_v2p[p][j];
            float a1 = bn1[j] * rsqrtf(bn1[3 * H1 + j] + EPSF);
            r += (a1 * b1[j] + bn1[H1 + j] - bn1[2 * H1 + j] * a1) * v2;
        }
        if (j < H2) {
            float v3 = 0.f;
            #pragma unroll
            for (int p = 0; p < CG; p++) v3 += g_v3p[p][j];
            float a2 = bn2[j] * rsqrtf(bn2[3 * H2 + j] + EPSF);
            r += (a2 * b2[j] + bn2[H2 + j] - bn2[2 * H2 + j] * a2) * v3;
        }
        if (j < H3) {
            float a3 = bn3[j] * rsqrtf(bn3[3 * H3 + j] + EPSF);
            r += (a3 * b3[j] + bn3[H3 + j] - bn3[2 * H3 + j] * a3) * pred_w[D0 + j];
        }
        if (j == 0) r += pred_b[0];

        r = warp_sum(r);
        if ((tid & 31) == 0) red[tid >> 5] = r;
        __syncthreads();
        if (tid == 0) {
            float rb = 0.f;
            #pragma unroll
            for (int w = 0; w < 8; w++) rb += red[w];
            g_rp[bid] = rb;
        }
    }
}

// ---------------------------------------------------------------------------
// Main gather kernel: 512 threads (16 warps), 2 rows per warp, 32 rows/block,
// grid 128.  Coefficient LDS loads serve both rows -> smem traffic halved.
__global__ __launch_bounds__(512) void k_main(
    const float* __restrict__ numb, const int* __restrict__ cat,
    const float* __restrict__ emb,  const float* __restrict__ cross_w,
    const float* __restrict__ cross_b, const float* __restrict__ pred_w,
    float* __restrict__ out) {

    __shared__ float2 sv0[832], sv1[832], sv2[832], sv3[832], sv4[832];
    __shared__ float  s_qn[16];
    __shared__ float  red[3][16];
    __shared__ float  s_sc[4];

    const int tid  = threadIdx.x;
    const int warp = tid >> 5;
    const int lane = tid & 31;
    const int rowA = blockIdx.x * 32 + warp * 2;
    const int rowB = rowA + 1;

    int miA = (lane < Fn) ? cat[rowA * Fn + lane] : 0;
    int miB = (lane < Fn) ? cat[rowB * Fn + lane] : 0;

    // ---- staging + Sc reductions ----
    {
        float p1 = 0.f, p2 = 0.f, p3 = 0.f;
        const float2* cwp = (const float2*)cross_w;
        const float2* pwp = (const float2*)pred_w;
        const float2* qp  = (const float2*)g_q;
        for (int k = tid; k < 832; k += 512) {
            float2 c0 = cwp[k];
            float2 c1 = cwp[832 + k];
            float2 c2 = cwp[1664 + k];
            float2 pw = pwp[k];
            sv0[k] = c0; sv1[k] = c1; sv2[k] = c2; sv3[k] = pw;
            sv4[k] = qp[k];
            p1 += c1.x + c1.y; p2 += c2.x + c2.y; p3 += pw.x + pw.y;
        }
        if (tid < NUMB) s_qn[tid] = g_q[D0 + tid];
        if (tid == 0) {
            float rt = 0.f;
            #pragma unroll
            for (int i = 0; i < 7; i++) rt += g_rp[i];
            s_sc[3] = rt;
        }
        p1 = warp_sum(p1); p2 = warp_sum(p2); p3 = warp_sum(p3);
        if (lane == 0) { red[0][warp] = p1; red[1][warp] = p2; red[2][warp] = p3; }
        __syncthreads();
        if (tid < 32) {
            float a = (tid < 16) ? red[0][tid] : 0.f;
            float b = (tid < 16) ? red[1][tid] : 0.f;
            float c = (tid < 16) ? red[2][tid] : 0.f;
            a = warp_sum(a); b = warp_sum(b); c = warp_sum(c);
            if (tid == 0) { s_sc[0] = a; s_sc[1] = b; s_sc[2] = c; }
        }
        __syncthreads();
    }

    // ---- gather: 5 dots for 2 rows ----
    float a0A = 0.f, a1A = 0.f, a2A = 0.f, a3A = 0.f, a4A = 0.f;
    float a0B = 0.f, a1B = 0.f, a2B = 0.f, a3B = 0.f, a4B = 0.f;

    #pragma unroll
    for (int f = 0; f < Fn; f++) {
        int iA = __shfl_sync(0xffffffffu, miA, f);
        int iB = __shfl_sync(0xffffffffu, miB, f);
        const float2* base = reinterpret_cast<const float2*>(
            emb + (size_t)f * (Vn * Dn));
        float2 eA = base[(size_t)iA * 32 + lane];
        float2 eB = base[(size_t)iB * 32 + lane];
        int b = f * 32 + lane;
        float2 c;
        c = sv0[b]; a0A += eA.x * c.x + eA.y * c.y; a0B += eB.x * c.x + eB.y * c.y;
        c = sv1[b]; a1A += eA.x * c.x + eA.y * c.y; a1B += eB.x * c.x + eB.y * c.y;
        c = sv2[b]; a2A += eA.x * c.x + eA.y * c.y; a2B += eB.x * c.x + eB.y * c.y;
        c = sv3[b]; a3A += eA.x * c.x + eA.y * c.y; a3B += eB.x * c.x + eB.y * c.y;
        c = sv4[b]; a4A += eA.x * c.x + eA.y * c.y; a4B += eB.x * c.x + eB.y * c.y;
    }
    if (lane < NUMB) {
        a4A += numb[rowA * NUMB + lane] * s_qn[lane];
        a4B += numb[rowB * NUMB + lane] * s_qn[lane];
    }

    a0A = warp_sum(a0A); a1A = warp_sum(a1A); a2A = warp_sum(a2A);
    a3A = warp_sum(a3A); a4A = warp_sum(a4A);
    a0B = warp_sum(a0B); a1B = warp_sum(a1B); a2B = warp_sum(a2B);
    a3B = warp_sum(a3B); a4B = warp_sum(a4B);

    if (lane < 2) {
        float d0 = (lane == 0) ? a0A : a0B;
        float d1 = (lane == 0) ? a1A : a1B;
        float d2 = (lane == 0) ? a2A : a2B;
        float d3 = (lane == 0) ? a3A : a3B;
        float d4 = (lane == 0) ? a4A : a4B;
        int   rw = (lane == 0) ? rowA : rowB;

        float cb0 = cross_b[0], cb1 = cross_b[1], cb2 = cross_b[2];
        float Sc1 = s_sc[0], Sc2 = s_sc[1], Sp = s_sc[2], rtot = s_sc[3];

        float al = d0 + 1.f;
        float be = cb0;
        float sd1 = al * d1 + be * Sc1;
        al = (sd1 + 1.f) * al;
        be = (sd1 + 1.f) * be + cb1;
        float sd2 = al * d2 + be * Sc2;
        al = (sd2 + 1.f) * al;
        be = (sd2 + 1.f) * be + cb2;

        float z = al * d3 + be * Sp + d4 + rtot;
        out[rw] = 1.f / (1.f + expf(-z));
    }
}

// ---------------------------------------------------------------------------
extern "C" void kernel_launch(void* const* d_in, const int* in_sizes, int n_in,
                              void* d_out, int out_size) {
    const float* numb    = (const float*)d_in[0];
    const int*   cat     = (const int*)  d_in[1];
    const float* emb     = (const float*)d_in[2];
    const float* bn0     = (const float*)d_in[3];
    const float* w1      = (const float*)d_in[4];
    const float* b1      = (const float*)d_in[5];
    const float* bn1     = (const float*)d_in[6];
    const float* w2      = (const float*)d_in[7];
    const float* b2      = (const float*)d_in[8];
    const float* bn2     = (const float*)d_in[9];
    const float* w3      = (const float*)d_in[10];
    const float* b3      = (const float*)d_in[11];
    const float* bn3     = (const float*)d_in[12];
    const float* cross_w = (const float*)d_in[13];
    const float* cross_b = (const float*)d_in[14];
    const float* pred_w  = (const float*)d_in[15];
    const float* pred_b  = (const float*)d_in[16];
    float* out = (float*)d_out;

    k_chain<<<CG, 256>>>(bn0, w1, b1, bn1, w2, b2, bn2, w3, b3, bn3, pred_w, pred_b);
    k_main<<<Bn / 32, 512>>>(numb, cat, emb, cross_w, cross_b, pred_w, out);
}

// round 5
// speedup vs baseline: 1.3266x; 1.3266x over previous
#include <cuda_runtime.h>
#include <math.h>

// DCN collapsed-affine, round 5:
//  - 3 chain kernels (v3, v2, u partials); scalar r accumulated via atomicAdd
//    contributions inside the chain (linear decomposition), no k_scalars.
//  - k_main: 1024 thr, grid 128, split-F warps (2 rows x 13 features per warp)
//    -> half the coefficient smem traffic at full occupancy; q computed in
//    the prologue from u-partials.

#define EPSF 1e-5f

constexpr int Bn   = 4096;
constexpr int Fn   = 26;
constexpr int Vn   = 10000;
constexpr int Dn   = 64;
constexpr int D0   = 1664;   // Fn*Dn
constexpr int NUMB = 13;
constexpr int INW  = 1677;   // D0 + NUMB
constexpr int H1   = 1024;
constexpr int H2   = 512;
constexpr int H3   = 256;

// Scratch (device globals)
__device__ float g_v3p[16][H2];   // v3 partials (16 i-chunks of 16)
__device__ float g_v2p[8][H1];    // v2 partials (8 i-chunks of 64)
__device__ float g_up[8][1792];   // u partials  (8 i-chunks of 128)
__device__ float g_r;             // scalar r (reset by k_v3, atomics in v2/u)

__device__ __forceinline__ float warp_sum(float v) {
    #pragma unroll
    for (int o = 16; o; o >>= 1) v += __shfl_xor_sync(0xffffffffu, v, o);
    return v;
}

// ---------------------------------------------------------------------------
// v3 partials: grid 32 = (ib 16) x (jb 2), block 256.
// v3p[ib][j] = sum_{i in 16-chunk} w3[i,j] * (a3[i]*pw_h[i])
// Also: block 0 resets g_r = pred_b (no atomics in this kernel -> race-free).
__global__ __launch_bounds__(256) void k_v3(
    const float* __restrict__ w3, const float* __restrict__ bn3,
    const float* __restrict__ pred_w, const float* __restrict__ pred_b) {
    int bid = blockIdx.x;
    int ib = bid >> 1, jb = bid & 1;
    int t = threadIdx.x;
    int i0 = ib * 16;
    __shared__ float ts[16];
    if (t < 16) {
        int i = i0 + t;
        float a3 = bn3[i] * rsqrtf(bn3[3 * H3 + i] + EPSF);
        ts[t] = a3 * pred_w[D0 + i];
    }
    if (bid == 0 && t == 0) g_r = pred_b[0];
    __syncthreads();
    int j = jb * 256 + t;
    float acc = 0.f;
    #pragma unroll
    for (int i = 0; i < 16; i++) acc += w3[(i0 + i) * H2 + j] * ts[i];
    g_v3p[ib][j] = acc;
}

// ---------------------------------------------------------------------------
// v2 partials: grid 64 = (ib 8) x (jb 8), block 128.
// Also accumulates into g_r: d2.v3 (jb==0 blocks) and d3.pw_h (block 0).
__global__ __launch_bounds__(128) void k_v2(
    const float* __restrict__ w2, const float* __restrict__ bn2,
    const float* __restrict__ b2, const float* __restrict__ bn3,
    const float* __restrict__ b3, const float* __restrict__ pred_w) {
    int bid = blockIdx.x;
    int jb = bid & 7, ib = bid >> 3;
    int t = threadIdx.x;
    int i0 = ib * 64;
    __shared__ float ts[64];
    __shared__ float red[4];
    float rloc = 0.f;

    if (t < 64) {
        int i = i0 + t;
        float v3 = 0.f;
        #pragma unroll
        for (int p = 0; p < 16; p++) v3 += g_v3p[p][i];
        float a2 = bn2[i] * rsqrtf(bn2[3 * H2 + i] + EPSF);
        ts[t] = a2 * v3;
        if (jb == 0)
            rloc += (a2 * b2[i] + bn2[H2 + i] - bn2[2 * H2 + i] * a2) * v3;
    }
    if (bid == 0) {   // d3 . pw_h over 256 terms
        #pragma unroll
        for (int i = t; i < H3; i += 128) {
            float a3 = bn3[i] * rsqrtf(bn3[3 * H3 + i] + EPSF);
            rloc += (a3 * b3[i] + bn3[H3 + i] - bn3[2 * H3 + i] * a3) * pred_w[D0 + i];
        }
    }
    __syncthreads();

    int j = jb * 128 + t;
    float acc = 0.f;
    #pragma unroll 8
    for (int i = 0; i < 64; i++) acc += w2[(i0 + i) * H1 + j] * ts[i];
    g_v2p[ib][j] = acc;

    if (jb == 0) {
        rloc = warp_sum(rloc);
        if ((t & 31) == 0) red[t >> 5] = rloc;
        __syncthreads();
        if (t == 0) atomicAdd(&g_r, red[0] + red[1] + red[2] + red[3]);
    }
}

// ---------------------------------------------------------------------------
// u partials: grid 112 = (ib 8) x (jb 14), block 128.
// Also accumulates into g_r: d1.v2 (jb==0 blocks) and c0 . u_partial (all).
__global__ __launch_bounds__(128) void k_u(
    const float* __restrict__ w1, const float* __restrict__ bn1,
    const float* __restrict__ b1, const float* __restrict__ bn0) {
    int bid = blockIdx.x;
    int jb = bid % 14, ib = bid / 14;
    int t = threadIdx.x;
    int i0 = ib * 128;
    __shared__ float ts[128];
    __shared__ float red[4];
    float rloc = 0.f;

    {
        int i = i0 + t;
        float v2 = 0.f;
        #pragma unroll
        for (int p = 0; p < 8; p++) v2 += g_v2p[p][i];
        float a1 = bn1[i] * rsqrtf(bn1[3 * H1 + i] + EPSF);
        ts[t] = a1 * v2;
        if (jb == 0)
            rloc += (a1 * b1[i] + bn1[H1 + i] - bn1[2 * H1 + i] * a1) * v2;
    }
    __syncthreads();

    int j = jb * 128 + t;
    if (j < INW) {
        float acc = 0.f;
        #pragma unroll 8
        for (int i = 0; i < 128; i++)
            acc += w1[(size_t)(i0 + i) * INW + j] * ts[i];
        g_up[ib][j] = acc;
        // c0 . u contribution (linear over partials)
        float a0 = bn0[j] * rsqrtf(bn0[3 * INW + j] + EPSF);
        float c0 = bn0[INW + j] - bn0[2 * INW + j] * a0;
        rloc += c0 * acc;
    }

    rloc = warp_sum(rloc);
    if ((t & 31) == 0) red[t >> 5] = rloc;
    __syncthreads();
    if (t == 0) atomicAdd(&g_r, red[0] + red[1] + red[2] + red[3]);
}

// ---------------------------------------------------------------------------
// Main gather kernel: 1024 thr (32 warps), grid 128.
// Warp w: row-pair (w & 15), feature-half (w >> 4): 2 rows x 13 features.
// Prologue: stage coefficient vectors, compute q from u-partials, Sc sums.
__global__ __launch_bounds__(1024) void k_main(
    const float* __restrict__ numb, const int* __restrict__ cat,
    const float* __restrict__ emb,  const float* __restrict__ cross_w,
    const float* __restrict__ cross_b, const float* __restrict__ pred_w,
    const float* __restrict__ bn0, float* __restrict__ out) {

    __shared__ float2 sv0[832], sv1[832], sv2[832], sv3[832], sv4[832];
    __shared__ float  s_qn[16];
    __shared__ float  redm[3][32];
    __shared__ float  s_sc[4];               // Sc1, Sc2, Sp, rtot
    __shared__ float  part[16][2][10];       // [pair][half][rs*5 + comp]

    const int tid  = threadIdx.x;
    const int warp = tid >> 5;
    const int lane = tid & 31;
    const int pair = warp & 15;
    const int half = warp >> 4;
    const int f0   = half * 13;
    const int rowA = blockIdx.x * 32 + pair * 2;
    const int rowB = rowA + 1;

    int miA = (lane < 13) ? cat[rowA * Fn + f0 + lane] : 0;
    int miB = (lane < 13) ? cat[rowB * Fn + f0 + lane] : 0;

    // ---- prologue: staging + q + Sc sums ----
    float p1 = 0.f, p2 = 0.f, p3 = 0.f;
    {
        const float2* cwp = (const float2*)cross_w;
        const float2* pwp = (const float2*)pred_w;
        if (tid < 832) {
            float2 c0 = cwp[tid];
            float2 c1 = cwp[832 + tid];
            float2 c2 = cwp[1664 + tid];
            float2 pw = pwp[tid];
            sv0[tid] = c0; sv1[tid] = c1; sv2[tid] = c2; sv3[tid] = pw;
            p1 = c1.x + c1.y; p2 = c2.x + c2.y; p3 = pw.x + pw.y;
        }
        float* sv4f = (float*)sv4;
        {
            int j = tid;                 // 0..1023 < D0
            float u = 0.f;
            #pragma unroll
            for (int p = 0; p < 8; p++) u += g_up[p][j];
            float a0 = bn0[j] * rsqrtf(bn0[3 * INW + j] + EPSF);
            sv4f[j] = a0 * u;
        }
        {
            int j = tid + 1024;          // 1024..2047
            if (j < INW) {
                float u = 0.f;
                #pragma unroll
                for (int p = 0; p < 8; p++) u += g_up[p][j];
                float a0 = bn0[j] * rsqrtf(bn0[3 * INW + j] + EPSF);
                float q = a0 * u;
                if (j < D0) sv4f[j] = q;
                else        s_qn[j - D0] = q;
            }
        }
        if (tid == 0) s_sc[3] = g_r;
    }
    p1 = warp_sum(p1); p2 = warp_sum(p2); p3 = warp_sum(p3);
    if (lane == 0) { redm[0][warp] = p1; redm[1][warp] = p2; redm[2][warp] = p3; }
    __syncthreads();
    if (tid < 32) {
        float a = warp_sum(redm[0][tid]);
        float b = warp_sum(redm[1][tid]);
        float c = warp_sum(redm[2][tid]);
        if (tid == 0) { s_sc[0] = a; s_sc[1] = b; s_sc[2] = c; }
    }
    __syncthreads();

    // ---- gather: 13 features x 2 rows per warp ----
    float a0A = 0.f, a1A = 0.f, a2A = 0.f, a3A = 0.f, a4A = 0.f;
    float a0B = 0.f, a1B = 0.f, a2B = 0.f, a3B = 0.f, a4B = 0.f;

    #pragma unroll
    for (int ff = 0; ff < 13; ff++) {
        int f  = f0 + ff;
        int iA = __shfl_sync(0xffffffffu, miA, ff);
        int iB = __shfl_sync(0xffffffffu, miB, ff);
        const float2* base = reinterpret_cast<const float2*>(
            emb + (size_t)f * (Vn * Dn));
        float2 eA = base[(size_t)iA * 32 + lane];
        float2 eB = base[(size_t)iB * 32 + lane];
        int b = f * 32 + lane;
        float2 c;
        c = sv0[b]; a0A += eA.x * c.x + eA.y * c.y; a0B += eB.x * c.x + eB.y * c.y;
        c = sv1[b]; a1A += eA.x * c.x + eA.y * c.y; a1B += eB.x * c.x + eB.y * c.y;
        c = sv2[b]; a2A += eA.x * c.x + eA.y * c.y; a2B += eB.x * c.x + eB.y * c.y;
        c = sv3[b]; a3A += eA.x * c.x + eA.y * c.y; a3B += eB.x * c.x + eB.y * c.y;
        c = sv4[b]; a4A += eA.x * c.x + eA.y * c.y; a4B += eB.x * c.x + eB.y * c.y;
    }
    if (half == 1 && lane < NUMB) {   // numb dot rides with the f-half-1 warps
        float qn = s_qn[lane];
        a4A += numb[rowA * NUMB + lane] * qn;
        a4B += numb[rowB * NUMB + lane] * qn;
    }

    a0A = warp_sum(a0A); a1A = warp_sum(a1A); a2A = warp_sum(a2A);
    a3A = warp_sum(a3A); a4A = warp_sum(a4A);
    a0B = warp_sum(a0B); a1B = warp_sum(a1B); a2B = warp_sum(a2B);
    a3B = warp_sum(a3B); a4B = warp_sum(a4B);

    if (lane == 0) {
        part[pair][half][0] = a0A; part[pair][half][1] = a1A;
        part[pair][half][2] = a2A; part[pair][half][3] = a3A;
        part[pair][half][4] = a4A;
        part[pair][half][5] = a0B; part[pair][half][6] = a1B;
        part[pair][half][7] = a2B; part[pair][half][8] = a3B;
        part[pair][half][9] = a4B;
    }
    __syncthreads();

    // ---- epilogue: 32 threads, one per row ----
    if (tid < 32) {
        int p  = tid >> 1;
        int rs = (tid & 1) * 5;
        float d0 = part[p][0][rs + 0] + part[p][1][rs + 0];
        float d1 = part[p][0][rs + 1] + part[p][1][rs + 1];
        float d2 = part[p][0][rs + 2] + part[p][1][rs + 2];
        float d3 = part[p][0][rs + 3] + part[p][1][rs + 3];
        float d4 = part[p][0][rs + 4] + part[p][1][rs + 4];

        float cb0 = cross_b[0], cb1 = cross_b[1], cb2 = cross_b[2];
        float Sc1 = s_sc[0], Sc2 = s_sc[1], Sp = s_sc[2], rtot = s_sc[3];

        float al = d0 + 1.f;
        float be = cb0;
        float sd1 = al * d1 + be * Sc1;
        al = (sd1 + 1.f) * al;
        be = (sd1 + 1.f) * be + cb1;
        float sd2 = al * d2 + be * Sc2;
        al = (sd2 + 1.f) * al;
        be = (sd2 + 1.f) * be + cb2;

        float z = al * d3 + be * Sp + d4 + rtot;
        out[blockIdx.x * 32 + tid] = 1.f / (1.f + expf(-z));
    }
}

// ---------------------------------------------------------------------------
extern "C" void kernel_launch(void* const* d_in, const int* in_sizes, int n_in,
                              void* d_out, int out_size) {
    const float* numb    = (const float*)d_in[0];
    const int*   cat     = (const int*)  d_in[1];
    const float* emb     = (const float*)d_in[2];
    const float* bn0     = (const float*)d_in[3];
    const float* w1      = (const float*)d_in[4];
    const float* b1      = (const float*)d_in[5];
    const float* bn1     = (const float*)d_in[6];
    const float* w2      = (const float*)d_in[7];
    const float* b2      = (const float*)d_in[8];
    const float* bn2     = (const float*)d_in[9];
    const float* w3      = (const float*)d_in[10];
    const float* b3      = (const float*)d_in[11];
    const float* bn3     = (const float*)d_in[12];
    const float* cross_w = (const float*)d_in[13];
    const float* cross_b = (const float*)d_in[14];
    const float* pred_w  = (const float*)d_in[15];
    const float* pred_b  = (const float*)d_in[16];
    float* out = (float*)d_out;

    k_v3<<<32, 256>>>(w3, bn3, pred_w, pred_b);
    k_v2<<<64, 128>>>(w2, bn2, b2, bn3, b3, pred_w);
    k_u<<<112, 128>>>(w1, bn1, b1, bn0);
    k_main<<<128, 1024>>>(numb, cat, emb, cross_w, cross_b, pred_w, bn0, out);
}

// round 6
// speedup vs baseline: 1.9908x; 1.5008x over previous
#include <cuda_runtime.h>
#include <math.h>

// DCN collapsed-affine, round 6:
//  - chain kernels widened; u accumulated via atomicAdd into a single vector
//  - k_main: 1 row/warp, 1024 thr, grid 128, explicit depth-4 gather pipeline

#define EPSF 1e-5f

constexpr int Bn   = 4096;
constexpr int Fn   = 26;
constexpr int Vn   = 10000;
constexpr int Dn   = 64;
constexpr int D0   = 1664;   // Fn*Dn
constexpr int NUMB = 13;
constexpr int INW  = 1677;   // D0 + NUMB
constexpr int H1   = 1024;
constexpr int H2   = 512;
constexpr int H3   = 256;

// Scratch (device globals)
__device__ float g_v3p[16][H2];   // v3 partials (16 i-chunks of 16)
__device__ float g_v2p[16][H1];   // v2 partials (16 i-chunks of 32)
__device__ float g_u[1792];       // u (atomic-accumulated; zeroed in k_v3)
__device__ float g_r;             // scalar r

__device__ __forceinline__ float warp_sum(float v) {
    #pragma unroll
    for (int o = 16; o; o >>= 1) v += __shfl_xor_sync(0xffffffffu, v, o);
    return v;
}

// ---------------------------------------------------------------------------
// v3 partials: grid 32 = ib(16) x jb(2), block 256. Also zeroes g_u, sets g_r.
__global__ __launch_bounds__(256) void k_v3(
    const float* __restrict__ w3, const float* __restrict__ bn3,
    const float* __restrict__ pred_w, const float* __restrict__ pred_b) {
    int bid = blockIdx.x;
    int ib = bid >> 1, jb = bid & 1;
    int t = threadIdx.x;
    int i0 = ib * 16;
    __shared__ float ts[16];
    if (t < 16) {
        int i = i0 + t;
        float a3 = bn3[i] * rsqrtf(bn3[3 * H3 + i] + EPSF);
        ts[t] = a3 * pred_w[D0 + i];
    }
    int gt = bid * 256 + t;
    if (gt < 1792) g_u[gt] = 0.f;
    if (gt == 0) g_r = pred_b[0];
    __syncthreads();
    int j = jb * 256 + t;
    float acc = 0.f;
    #pragma unroll
    for (int i = 0; i < 16; i++) acc += w3[(i0 + i) * H2 + j] * ts[i];
    g_v3p[ib][j] = acc;
}

// ---------------------------------------------------------------------------
// v2 partials: grid 128 = ib(16, chunk 32) x jb(8, 128 cols), block 128.
// Adds d2.v3 (jb==0 blocks) and d3.pw_h (block 0) to g_r.
__global__ __launch_bounds__(128) void k_v2(
    const float* __restrict__ w2, const float* __restrict__ bn2,
    const float* __restrict__ b2, const float* __restrict__ bn3,
    const float* __restrict__ b3, const float* __restrict__ pred_w) {
    int bid = blockIdx.x;
    int jb = bid & 7, ib = bid >> 3;
    int t = threadIdx.x;
    int i0 = ib * 32;
    __shared__ float ts[32];
    __shared__ float red[4];
    float rloc = 0.f;

    if (t < 32) {
        int i = i0 + t;
        float v3 = 0.f;
        #pragma unroll
        for (int p = 0; p < 16; p++) v3 += g_v3p[p][i];
        float a2 = bn2[i] * rsqrtf(bn2[3 * H2 + i] + EPSF);
        ts[t] = a2 * v3;
        if (jb == 0)
            rloc += (a2 * b2[i] + bn2[H2 + i] - bn2[2 * H2 + i] * a2) * v3;
    }
    if (bid == 0) {
        #pragma unroll
        for (int i = t; i < H3; i += 128) {
            float a3 = bn3[i] * rsqrtf(bn3[3 * H3 + i] + EPSF);
            rloc += (a3 * b3[i] + bn3[H3 + i] - bn3[2 * H3 + i] * a3) * pred_w[D0 + i];
        }
    }
    __syncthreads();

    int j = jb * 128 + t;
    float acc = 0.f;
    #pragma unroll 8
    for (int i = 0; i < 32; i++) acc += w2[(i0 + i) * H1 + j] * ts[i];
    g_v2p[ib][j] = acc;

    if (jb == 0) {
        rloc = warp_sum(rloc);
        if ((t & 31) == 0) red[t >> 5] = rloc;
        __syncthreads();
        if (t == 0) atomicAdd(&g_r, red[0] + red[1] + red[2] + red[3]);
    }
}

// ---------------------------------------------------------------------------
// u: grid 112 = ib(16, chunk 64) x jb(7, 256 cols), block 256.
// atomicAdds partial u into g_u; adds d1.v2 (jb==0) and c0.u_partial to g_r.
__global__ __launch_bounds__(256) void k_u(
    const float* __restrict__ w1, const float* __restrict__ bn1,
    const float* __restrict__ b1, const float* __restrict__ bn0) {
    int bid = blockIdx.x;
    int jb = bid % 7, ib = bid / 7;
    int t = threadIdx.x;
    int i0 = ib * 64;
    __shared__ float ts[64];
    __shared__ float red[8];
    float rloc = 0.f;

    if (t < 64) {
        int i = i0 + t;
        float v2 = 0.f;
        #pragma unroll
        for (int p = 0; p < 16; p++) v2 += g_v2p[p][i];
        float a1 = bn1[i] * rsqrtf(bn1[3 * H1 + i] + EPSF);
        ts[t] = a1 * v2;
        if (jb == 0)
            rloc += (a1 * b1[i] + bn1[H1 + i] - bn1[2 * H1 + i] * a1) * v2;
    }
    __syncthreads();

    int j = jb * 256 + t;
    if (j < INW) {
        float acc = 0.f;
        #pragma unroll 16
        for (int i = 0; i < 64; i++)
            acc += w1[(size_t)(i0 + i) * INW + j] * ts[i];
        atomicAdd(&g_u[j], acc);
        float a0 = bn0[j] * rsqrtf(bn0[3 * INW + j] + EPSF);
        float c0 = bn0[INW + j] - bn0[2 * INW + j] * a0;
        rloc += c0 * acc;
    }

    rloc = warp_sum(rloc);
    if ((t & 31) == 0) red[t >> 5] = rloc;
    __syncthreads();
    if (t == 0) {
        float rb = 0.f;
        #pragma unroll
        for (int w = 0; w < 8; w++) rb += red[w];
        atomicAdd(&g_r, rb);
    }
}

// ---------------------------------------------------------------------------
// Main gather kernel: 1024 thr (32 warps), grid 128, 1 row/warp,
// explicit depth-4 float2 prefetch pipeline for the embedding gather.
__global__ __launch_bounds__(1024) void k_main(
    const float* __restrict__ numb, const int* __restrict__ cat,
    const float* __restrict__ emb,  const float* __restrict__ cross_w,
    const float* __restrict__ cross_b, const float* __restrict__ pred_w,
    const float* __restrict__ bn0, float* __restrict__ out) {

    __shared__ float2 sv0[832], sv1[832], sv2[832], sv3[832], sv4[832];
    __shared__ float  s_qn[16];
    __shared__ float  redm[3][32];
    __shared__ float  s_sc[4];

    const int tid  = threadIdx.x;
    const int warp = tid >> 5;
    const int lane = tid & 31;
    const int row  = blockIdx.x * 32 + warp;

    int mi = (lane < Fn) ? cat[row * Fn + lane] : 0;

    // ---- prologue: staging, q from g_u, Sc sums ----
    float p1 = 0.f, p2 = 0.f, p3 = 0.f;
    {
        const float2* cwp = (const float2*)cross_w;
        const float2* pwp = (const float2*)pred_w;
        if (tid < 832) {
            float2 c0 = cwp[tid];
            float2 c1 = cwp[832 + tid];
            float2 c2 = cwp[1664 + tid];
            float2 pw = pwp[tid];
            sv0[tid] = c0; sv1[tid] = c1; sv2[tid] = c2; sv3[tid] = pw;
            p1 = c1.x + c1.y; p2 = c2.x + c2.y; p3 = pw.x + pw.y;
        }
        float* sv4f = (float*)sv4;
        {
            int j = tid;                 // < D0
            float a0 = bn0[j] * rsqrtf(bn0[3 * INW + j] + EPSF);
            sv4f[j] = a0 * g_u[j];
        }
        {
            int j = tid + 1024;
            if (j < INW) {
                float a0 = bn0[j] * rsqrtf(bn0[3 * INW + j] + EPSF);
                float q = a0 * g_u[j];
                if (j < D0) sv4f[j] = q;
                else        s_qn[j - D0] = q;
            }
        }
        if (tid == 0) s_sc[3] = g_r;
    }
    p1 = warp_sum(p1); p2 = warp_sum(p2); p3 = warp_sum(p3);
    if (lane == 0) { redm[0][warp] = p1; redm[1][warp] = p2; redm[2][warp] = p3; }
    __syncthreads();
    if (tid < 32) {
        float a = warp_sum(redm[0][tid]);
        float b = warp_sum(redm[1][tid]);
        float c = warp_sum(redm[2][tid]);
        if (tid == 0) { s_sc[0] = a; s_sc[1] = b; s_sc[2] = c; }
    }
    __syncthreads();

    // ---- gather with depth-4 prefetch ----
    float acc0 = 0.f, acc1 = 0.f, acc2 = 0.f, acc3 = 0.f, acc4 = 0.f;

    #define EMB_LD(F) \
        __ldg(reinterpret_cast<const float2*>(emb + (size_t)(F) * (Vn * Dn)) \
              + (size_t)__shfl_sync(0xffffffffu, mi, (F)) * 32 + lane)

    float2 e0 = EMB_LD(0);
    float2 e1 = EMB_LD(1);
    float2 e2 = EMB_LD(2);
    float2 e3 = EMB_LD(3);

    #pragma unroll
    for (int f = 0; f < Fn; f++) {
        float2 e = e0;
        e0 = e1; e1 = e2; e2 = e3;
        if (f + 4 < Fn) e3 = EMB_LD(f + 4);
        int b = f * 32 + lane;
        float2 c;
        c = sv0[b]; acc0 += e.x * c.x + e.y * c.y;
        c = sv1[b]; acc1 += e.x * c.x + e.y * c.y;
        c = sv2[b]; acc2 += e.x * c.x + e.y * c.y;
        c = sv3[b]; acc3 += e.x * c.x + e.y * c.y;
        c = sv4[b]; acc4 += e.x * c.x + e.y * c.y;
    }
    #undef EMB_LD

    if (lane < NUMB) acc4 += numb[row * NUMB + lane] * s_qn[lane];

    acc0 = warp_sum(acc0);
    acc1 = warp_sum(acc1);
    acc2 = warp_sum(acc2);
    acc3 = warp_sum(acc3);
    acc4 = warp_sum(acc4);

    if (lane == 0) {
        float cb0 = cross_b[0], cb1 = cross_b[1], cb2 = cross_b[2];
        float Sc1 = s_sc[0], Sc2 = s_sc[1], Sp = s_sc[2], rtot = s_sc[3];

        float al = acc0 + 1.f;
        float be = cb0;
        float sd1 = al * acc1 + be * Sc1;
        al = (sd1 + 1.f) * al;
        be = (sd1 + 1.f) * be + cb1;
        float sd2 = al * acc2 + be * Sc2;
        al = (sd2 + 1.f) * al;
        be = (sd2 + 1.f) * be + cb2;

        float z = al * acc3 + be * Sp + acc4 + rtot;
        out[row] = 1.f / (1.f + expf(-z));
    }
}

// ---------------------------------------------------------------------------
extern "C" void kernel_launch(void* const* d_in, const int* in_sizes, int n_in,
                              void* d_out, int out_size) {
    const float* numb    = (const float*)d_in[0];
    const int*   cat     = (const int*)  d_in[1];
    const float* emb     = (const float*)d_in[2];
    const float* bn0     = (const float*)d_in[3];
    const float* w1      = (const float*)d_in[4];
    const float* b1      = (const float*)d_in[5];
    const float* bn1     = (const float*)d_in[6];
    const float* w2      = (const float*)d_in[7];
    const float* b2      = (const float*)d_in[8];
    const float* bn2     = (const float*)d_in[9];
    const float* w3      = (const float*)d_in[10];
    const float* b3      = (const float*)d_in[11];
    const float* bn3     = (const float*)d_in[12];
    const float* cross_w = (const float*)d_in[13];
    const float* cross_b = (const float*)d_in[14];
    const float* pred_w  = (const float*)d_in[15];
    const float* pred_b  = (const float*)d_in[16];
    float* out = (float*)d_out;

    k_v3<<<32, 256>>>(w3, bn3, pred_w, pred_b);
    k_v2<<<128, 128>>>(w2, bn2, b2, bn3, b3, pred_w);
    k_u<<<112, 256>>>(w1, bn1, b1, bn0);
    k_main<<<128, 1024>>>(numb, cat, emb, cross_w, cross_b, pred_w, bn0, out);
}